// round 3
// baseline (speedup 1.0000x reference)
#include <cuda_runtime.h>
#include <cuda_fp16.h>
#include <cstdint>

#define NNODES 10000
#define NEDGES 320000
#define CH     256

// ---- scratch (static device allocations; no cudaMalloc allowed) ----
__device__ __align__(16) float  g_H[NNODES * CH];          // node linear projection (fp32)
__device__ __align__(16) __half g_AB[NNODES * 2 * CH];     // [A | B] per node, fp16
__device__ __align__(16) float  g_AGG[NNODES * CH];        // aggregation buffer
__device__ int g_rowptr[NNODES + 1];
__device__ int g_cnt[NNODES];
__device__ int g_col[NEDGES];

__device__ __forceinline__ uint32_t sptr(const void* p) {
    return (uint32_t)__cvta_generic_to_shared(p);
}

// ============================================================================
// Tensor-core GEMM with split-fp16 (Markidis 3-term) for ~fp32 accuracy:
//   out[M, NOUT] = act(A[M,K]) @ W^T + bias
// Virtual K' = 3K:  A' = [a_hi | a_lo | a_hi],  W' = [w_hi | w_hi | w_lo]
//   (lo = fp32 residual of fp16 rounding; dropped lo*lo term ~2^-22)
// SPLITW: W is W_s1 [256, 512]; out col j<256 uses W_s1[j, :256] (+bias[j]),
//         col j>=256 uses W_s1[j-256, 256:] (no bias).
// RELU_IN applies relu to A on load. HALF_OUT stores fp16.
// Tiling: BM=128 BN=64 BK=32(half), 8 warps, warp tile 64x16, m16n8k16 mma,
// double-buffered smem, padded rows (BKP=40) for conflict-free ldmatrix.
// ============================================================================
template<bool RELU_IN, bool SPLITW, bool HALF_OUT>
__global__ void __launch_bounds__(256) mma_gemm(
    const float* __restrict__ A, const float* __restrict__ W,
    const float* __restrict__ bias, void* __restrict__ out_raw,
    int M, int K, int NOUT)
{
    constexpr int BM = 128, BN = 64, BK = 32, BKP = 40;
    __shared__ __align__(16) __half sA[2][BM * BKP];
    __shared__ __align__(16) __half sB[2][BN * BKP];

    const int tid  = threadIdx.x;
    const int lane = tid & 31;
    const int warp = tid >> 5;
    const int wm   = (warp & 1) * 64;   // warp row offset within block
    const int wn   = (warp >> 1) * 16;  // warp col offset within block
    const int bm   = blockIdx.x * BM;
    const int bn   = blockIdx.y * BN;
    const int nch  = (3 * K) / BK;      // chunks over virtual K' = 3K

    const int lrow = tid >> 3;          // 0..31
    const int lkq  = (tid & 7) * 4;     // 0,4,...,28

    float4 stA[4];
    float4 stB[2];

    float c[4][2][4];
    #pragma unroll
    for (int i = 0; i < 4; i++)
        #pragma unroll
        for (int j = 0; j < 2; j++)
            #pragma unroll
            for (int q = 0; q < 4; q++) c[i][j][q] = 0.f;

    // ---- stage: gmem -> regs (fp32), relu applied to A here ----
    auto loadRegs = [&](int ch) {
        int k0    = ch * BK;
        int reg   = k0 / K;            // 0,1,2 (region of virtual K')
        int kreal = k0 - reg * K;
        #pragma unroll
        for (int i = 0; i < 4; i++) {
            int gm = bm + lrow + 32 * i;
            float4 v = make_float4(0.f, 0.f, 0.f, 0.f);
            if (gm < M)
                v = *reinterpret_cast<const float4*>(&A[(size_t)gm * K + kreal + lkq]);
            if (RELU_IN) {
                v.x = fmaxf(v.x, 0.f); v.y = fmaxf(v.y, 0.f);
                v.z = fmaxf(v.z, 0.f); v.w = fmaxf(v.w, 0.f);
            }
            stA[i] = v;
        }
        #pragma unroll
        for (int i = 0; i < 2; i++) {
            int n = bn + lrow + 32 * i;
            const float* wp;
            if (SPLITW)
                wp = (n < CH) ? (W + (size_t)n * (2 * CH) + kreal + lkq)
                              : (W + (size_t)(n - CH) * (2 * CH) + CH + kreal + lkq);
            else
                wp = W + (size_t)n * K + kreal + lkq;
            stB[i] = *reinterpret_cast<const float4*>(wp);
        }
    };

    auto cvt4 = [&](float4 v, bool lo) -> uint2 {
        __half h0 = __float2half_rn(v.x);
        __half h1 = __float2half_rn(v.y);
        __half h2 = __float2half_rn(v.z);
        __half h3 = __float2half_rn(v.w);
        if (lo) {
            h0 = __float2half_rn(v.x - __half2float(h0));
            h1 = __float2half_rn(v.y - __half2float(h1));
            h2 = __float2half_rn(v.z - __half2float(h2));
            h3 = __float2half_rn(v.w - __half2float(h3));
        }
        __half2 p0 = __halves2half2(h0, h1);
        __half2 p1 = __halves2half2(h2, h3);
        uint2 u;
        u.x = *reinterpret_cast<unsigned*>(&p0);
        u.y = *reinterpret_cast<unsigned*>(&p1);
        return u;
    };

    // ---- stage: regs -> smem (fp16 with hi/lo split per region) ----
    auto stsStage = [&](int buf, int ch) {
        int reg = (ch * BK) / K;
        bool aLo = (reg == 1);   // A: [hi, lo, hi]
        bool wLo = (reg == 2);   // W: [hi, hi, lo]
        #pragma unroll
        for (int i = 0; i < 4; i++)
            *reinterpret_cast<uint2*>(&sA[buf][(lrow + 32 * i) * BKP + lkq]) = cvt4(stA[i], aLo);
        #pragma unroll
        for (int i = 0; i < 2; i++)
            *reinterpret_cast<uint2*>(&sB[buf][(lrow + 32 * i) * BKP + lkq]) = cvt4(stB[i], wLo);
    };

    // ---- compute one 32-k chunk ----
    auto compute = [&](int buf) {
        #pragma unroll
        for (int kk = 0; kk < 2; kk++) {
            uint32_t b0, b1, b2, b3;
            {
                const __half* p = &sB[buf][(wn + (lane & 15)) * BKP + kk * 16 + (lane >> 4) * 8];
                asm volatile("ldmatrix.sync.aligned.m8n8.x4.shared.b16 {%0,%1,%2,%3}, [%4];"
                             : "=r"(b0), "=r"(b1), "=r"(b2), "=r"(b3) : "r"(sptr(p)));
            }
            #pragma unroll
            for (int fi = 0; fi < 4; fi++) {
                uint32_t a0, a1, a2, a3;
                const __half* p = &sA[buf][(wm + fi * 16 + (lane & 15)) * BKP + kk * 16 + (lane >> 4) * 8];
                asm volatile("ldmatrix.sync.aligned.m8n8.x4.shared.b16 {%0,%1,%2,%3}, [%4];"
                             : "=r"(a0), "=r"(a1), "=r"(a2), "=r"(a3) : "r"(sptr(p)));
                asm volatile("mma.sync.aligned.m16n8k16.row.col.f32.f16.f16.f32 "
                             "{%0,%1,%2,%3}, {%4,%5,%6,%7}, {%8,%9}, {%0,%1,%2,%3};"
                             : "+f"(c[fi][0][0]), "+f"(c[fi][0][1]), "+f"(c[fi][0][2]), "+f"(c[fi][0][3])
                             : "r"(a0), "r"(a1), "r"(a2), "r"(a3), "r"(b0), "r"(b2));
                asm volatile("mma.sync.aligned.m16n8k16.row.col.f32.f16.f16.f32 "
                             "{%0,%1,%2,%3}, {%4,%5,%6,%7}, {%8,%9}, {%0,%1,%2,%3};"
                             : "+f"(c[fi][1][0]), "+f"(c[fi][1][1]), "+f"(c[fi][1][2]), "+f"(c[fi][1][3])
                             : "r"(a0), "r"(a1), "r"(a2), "r"(a3), "r"(b1), "r"(b3));
            }
        }
    };

    // ---- main loop (double buffered) ----
    loadRegs(0);
    stsStage(0, 0);
    __syncthreads();
    int buf = 0;
    for (int ch = 0; ch < nch; ch++) {
        if (ch + 1 < nch) loadRegs(ch + 1);
        compute(buf);
        if (ch + 1 < nch) stsStage(buf ^ 1, ch + 1);
        __syncthreads();
        buf ^= 1;
    }

    // ---- epilogue: +bias, store ----
    #pragma unroll
    for (int fi = 0; fi < 4; fi++) {
        int row0 = bm + wm + fi * 16 + (lane >> 2);
        #pragma unroll
        for (int fj = 0; fj < 2; fj++) {
            int col = bn + wn + fj * 8 + (lane & 3) * 2;
            float bx, by;
            if (SPLITW) {
                bx = (col < CH) ? bias[col] : 0.f;
                by = (col < CH) ? bias[col + 1] : 0.f;
            } else {
                bx = bias[col]; by = bias[col + 1];
            }
            float v0 = c[fi][fj][0] + bx, v1 = c[fi][fj][1] + by;
            float v2 = c[fi][fj][2] + bx, v3 = c[fi][fj][3] + by;
            if (HALF_OUT) {
                __half* o = reinterpret_cast<__half*>(out_raw);
                if (row0 < M)
                    *reinterpret_cast<__half2*>(&o[(size_t)row0 * NOUT + col]) = __floats2half2_rn(v0, v1);
                if (row0 + 8 < M)
                    *reinterpret_cast<__half2*>(&o[(size_t)(row0 + 8) * NOUT + col]) = __floats2half2_rn(v2, v3);
            } else {
                float* o = reinterpret_cast<float*>(out_raw);
                if (row0 < M)
                    *reinterpret_cast<float2*>(&o[(size_t)row0 * NOUT + col]) = make_float2(v0, v1);
                if (row0 + 8 < M)
                    *reinterpret_cast<float2*>(&o[(size_t)(row0 + 8) * NOUT + col]) = make_float2(v2, v3);
            }
        }
    }
}

// ============================================================================
// CSR build (per launch)
// ============================================================================
__global__ void zero_cnt_kernel() {
    int i = blockIdx.x * blockDim.x + threadIdx.x;
    if (i < NNODES) g_cnt[i] = 0;
}

__global__ void hist_kernel(const int* __restrict__ ei) {
    int e = blockIdx.x * blockDim.x + threadIdx.x;
    if (e < NEDGES) atomicAdd(&g_cnt[ei[NEDGES + e]], 1);
}

__global__ void scan_kernel() {  // single block, 1024 threads
    __shared__ int sh[1024];
    __shared__ int carry_s;
    if (threadIdx.x == 0) carry_s = 0;
    __syncthreads();
    for (int base = 0; base < NNODES; base += 1024) {
        int i = base + (int)threadIdx.x;
        int v = (i < NNODES) ? g_cnt[i] : 0;
        sh[threadIdx.x] = v;
        __syncthreads();
        #pragma unroll
        for (int off = 1; off < 1024; off <<= 1) {
            int tv = (threadIdx.x >= off) ? sh[threadIdx.x - off] : 0;
            __syncthreads();
            sh[threadIdx.x] += tv;
            __syncthreads();
        }
        int carry = carry_s;
        int incl = sh[threadIdx.x];
        if (i < NNODES) {
            g_rowptr[i] = carry + incl - v;
            g_cnt[i] = 0;
        }
        int c_new = carry + sh[1023];
        __syncthreads();
        if (threadIdx.x == 0) carry_s = c_new;
        __syncthreads();
    }
    if (threadIdx.x == 0) g_rowptr[NNODES] = carry_s;
}

__global__ void scatter_kernel(const int* __restrict__ ei) {
    int e = blockIdx.x * blockDim.x + threadIdx.x;
    if (e < NEDGES) {
        int s = ei[e];
        int d = ei[NEDGES + e];
        int pos = g_rowptr[d] + atomicAdd(&g_cnt[d], 1);
        g_col[pos] = s;
    }
}

// ============================================================================
// Fused score + aggregate: one warp per dst node (CSR), no atomics.
// ============================================================================
__global__ void __launch_bounds__(256) agg_kernel(
    const __half* __restrict__ AB, const float* __restrict__ H,
    const float* __restrict__ w2, const float* __restrict__ b2,
    float* __restrict__ agg)
{
    const int lane = threadIdx.x & 31;
    const int d    = blockIdx.x * (blockDim.x >> 5) + (threadIdx.x >> 5);
    if (d >= NNODES) return;

    const float4 w0 = *reinterpret_cast<const float4*>(&w2[lane * 8]);
    const float4 w1 = *reinterpret_cast<const float4*>(&w2[lane * 8 + 4]);
    const float  bb = b2[0];

    uint4 araw = *reinterpret_cast<const uint4*>(&AB[(size_t)d * (2 * CH) + lane * 8]);
    float2 a0 = __half22float2(*reinterpret_cast<__half2*>(&araw.x));
    float2 a1 = __half22float2(*reinterpret_cast<__half2*>(&araw.y));
    float2 a2 = __half22float2(*reinterpret_cast<__half2*>(&araw.z));
    float2 a3 = __half22float2(*reinterpret_cast<__half2*>(&araw.w));

    float acc0 = 0.f, acc1 = 0.f, acc2 = 0.f, acc3 = 0.f;
    float acc4 = 0.f, acc5 = 0.f, acc6 = 0.f, acc7 = 0.f;

    const int beg = g_rowptr[d];
    const int end = g_rowptr[d + 1];

    for (int i = beg - 1; i < end; ++i) {
        int s = (i < beg) ? d : g_col[i];

        uint4 braw = *reinterpret_cast<const uint4*>(&AB[(size_t)s * (2 * CH) + CH + lane * 8]);
        const float4* hp = reinterpret_cast<const float4*>(&H[(size_t)s * CH + lane * 8]);
        float4 h0 = hp[0], h1 = hp[1];

        float2 b0 = __half22float2(*reinterpret_cast<__half2*>(&braw.x));
        float2 b1 = __half22float2(*reinterpret_cast<__half2*>(&braw.y));
        float2 b2v = __half22float2(*reinterpret_cast<__half2*>(&braw.z));
        float2 b3 = __half22float2(*reinterpret_cast<__half2*>(&braw.w));

        float p;
        p  = fmaxf(a0.x + b0.x, 0.f) * w0.x;
        p += fmaxf(a0.y + b0.y, 0.f) * w0.y;
        p += fmaxf(a1.x + b1.x, 0.f) * w0.z;
        p += fmaxf(a1.y + b1.y, 0.f) * w0.w;
        p += fmaxf(a2.x + b2v.x, 0.f) * w1.x;
        p += fmaxf(a2.y + b2v.y, 0.f) * w1.y;
        p += fmaxf(a3.x + b3.x, 0.f) * w1.z;
        p += fmaxf(a3.y + b3.y, 0.f) * w1.w;

        #pragma unroll
        for (int off = 16; off > 0; off >>= 1)
            p += __shfl_xor_sync(0xffffffffu, p, off);

        float score = 1.f / (1.f + __expf(-(p + bb)));

        acc0 = fmaf(score, h0.x, acc0);
        acc1 = fmaf(score, h0.y, acc1);
        acc2 = fmaf(score, h0.z, acc2);
        acc3 = fmaf(score, h0.w, acc3);
        acc4 = fmaf(score, h1.x, acc4);
        acc5 = fmaf(score, h1.y, acc5);
        acc6 = fmaf(score, h1.z, acc6);
        acc7 = fmaf(score, h1.w, acc7);
    }

    float* op = &agg[(size_t)d * CH + lane * 8];
    *reinterpret_cast<float4*>(op)     = make_float4(acc0, acc1, acc2, acc3);
    *reinterpret_cast<float4*>(op + 4) = make_float4(acc4, acc5, acc6, acc7);
}

extern "C" void kernel_launch(void* const* d_in, const int* in_sizes, int n_in,
                              void* d_out, int out_size)
{
    (void)in_sizes; (void)n_in; (void)out_size;
    const float* x  = (const float*)d_in[0];
    const int*   ei = (const int*)d_in[1];
    const float* W_lin[3] = {(const float*)d_in[2],  (const float*)d_in[8],  (const float*)d_in[14]};
    const float* b_lin[3] = {(const float*)d_in[3],  (const float*)d_in[9],  (const float*)d_in[15]};
    const float* W_s1[3]  = {(const float*)d_in[4],  (const float*)d_in[10], (const float*)d_in[16]};
    const float* b_s1[3]  = {(const float*)d_in[5],  (const float*)d_in[11], (const float*)d_in[17]};
    const float* W_s2[3]  = {(const float*)d_in[6],  (const float*)d_in[12], (const float*)d_in[18]};
    const float* b_s2[3]  = {(const float*)d_in[7],  (const float*)d_in[13], (const float*)d_in[19]};

    float *H, *AGG;
    __half* AB;
    cudaGetSymbolAddress((void**)&H,   g_H);
    cudaGetSymbolAddress((void**)&AB,  g_AB);
    cudaGetSymbolAddress((void**)&AGG, g_AGG);
    float* out = (float*)d_out;

    const dim3 blk(256);
    const dim3 gH((NNODES + 127) / 128, CH / 64);        // (79, 4)
    const dim3 gAB((NNODES + 127) / 128, (2 * CH) / 64); // (79, 8)
    const int  agrid = (NNODES + 7) / 8;

    // ---- CSR build (dst-keyed) ----
    zero_cnt_kernel<<<(NNODES + 255) / 256, blk>>>();
    hist_kernel<<<(NEDGES + 255) / 256, blk>>>(ei);
    scan_kernel<<<1, 1024>>>();
    scatter_kernel<<<(NEDGES + 255) / 256, blk>>>(ei);

    // ---- layer 1 ----
    mma_gemm<false, false, false><<<gH,  blk>>>(x,   W_lin[0], b_lin[0], H,  NNODES, 64, CH);
    mma_gemm<false, true,  true ><<<gAB, blk>>>(H,   W_s1[0],  b_s1[0],  AB, NNODES, CH, 2 * CH);
    agg_kernel<<<agrid, blk>>>(AB, H, W_s2[0], b_s2[0], AGG);

    // ---- layer 2 ----
    mma_gemm<true,  false, false><<<gH,  blk>>>(AGG, W_lin[1], b_lin[1], H,  NNODES, CH, CH);
    mma_gemm<false, true,  true ><<<gAB, blk>>>(H,   W_s1[1],  b_s1[1],  AB, NNODES, CH, 2 * CH);
    agg_kernel<<<agrid, blk>>>(AB, H, W_s2[1], b_s2[1], AGG);

    // ---- layer 3 (writes d_out) ----
    mma_gemm<true,  false, false><<<gH,  blk>>>(AGG, W_lin[2], b_lin[2], H,  NNODES, CH, CH);
    mma_gemm<false, true,  true ><<<gAB, blk>>>(H,   W_s1[2],  b_s1[2],  AB, NNODES, CH, 2 * CH);
    agg_kernel<<<agrid, blk>>>(AB, H, W_s2[2], b_s2[2], out);
}

// round 4
// speedup vs baseline: 1.4047x; 1.4047x over previous
#include <cuda_runtime.h>
#include <cuda_fp16.h>
#include <cstdint>

#define NNODES 10000
#define NEDGES 320000
#define CH     256

// ---- scratch (static device allocations; no cudaMalloc allowed) ----
__device__ __align__(16) __half g_xhi[NNODES * 64];
__device__ __align__(16) __half g_xlo[NNODES * 64];
__device__ __align__(16) __half g_Hhi[NNODES * CH];
__device__ __align__(16) __half g_Hlo[NNODES * CH];
__device__ __align__(16) __half g_Ahi[NNODES * CH];   // relu(agg) split, next-layer input
__device__ __align__(16) __half g_Alo[NNODES * CH];
__device__ __align__(16) __half g_AB [NNODES * 2 * CH];
__device__ __align__(16) __half g_Wlhi[3][CH * CH];
__device__ __align__(16) __half g_Wllo[3][CH * CH];
__device__ __align__(16) __half g_Wshi[3][2 * CH * CH];
__device__ __align__(16) __half g_Wslo[3][2 * CH * CH];
__device__ float g_bfull[3][2 * CH];
__device__ int g_rowptr[NNODES + 1];
__device__ int g_cnt[NNODES];
__device__ int g_col[NEDGES];

__device__ __forceinline__ uint32_t sptr(const void* p) {
    return (uint32_t)__cvta_generic_to_shared(p);
}
__device__ __forceinline__ void cpa16(uint32_t dst, const void* src, bool pred) {
    int sz = pred ? 16 : 0;
    asm volatile("cp.async.cg.shared.global [%0], [%1], 16, %2;"
                 :: "r"(dst), "l"(src), "r"(sz));
}
__device__ __forceinline__ void cpa_commit() {
    asm volatile("cp.async.commit_group;" ::: "memory");
}

// ============================================================================
// One-shot fp32 -> (hi, lo) fp16 split conversions
// ============================================================================
__global__ void cvt_split(const float* __restrict__ src,
                          __half* __restrict__ hi, __half* __restrict__ lo, int n)
{
    int i = blockIdx.x * blockDim.x + threadIdx.x;
    if (i < n) {
        float v = src[i];
        __half h = __float2half_rn(v);
        hi[i] = h;
        lo[i] = __float2half_rn(v - __half2float(h));
    }
}

// W_s1 [256, 512] -> uniform [512, 256]: row j<256 = W_s1[j, :256] (+bias),
// row j>=256 = W_s1[j-256, 256:] (bias 0). Also emits padded bias.
__global__ void cvt_ws(const float* __restrict__ Ws1, const float* __restrict__ bs1,
                       __half* __restrict__ hi, __half* __restrict__ lo,
                       float* __restrict__ bfull)
{
    int i = blockIdx.x * blockDim.x + threadIdx.x;
    if (i < 2 * CH * CH) {
        int j = i >> 8, k = i & 255;
        float v = (j < CH) ? Ws1[j * (2 * CH) + k] : Ws1[(j - CH) * (2 * CH) + CH + k];
        __half h = __float2half_rn(v);
        hi[i] = h;
        lo[i] = __float2half_rn(v - __half2float(h));
    }
    if (i < 2 * CH) bfull[i] = (i < CH) ? bs1[i] : 0.f;
}

// ============================================================================
// Tensor-core GEMM, split-fp16 (Markidis 3-term), pre-split operands:
//   out = (Ahi+Alo)[M,K] @ (Whi+Wlo)[NOUT,K]^T + bias  (lo*lo dropped, ~2^-22)
// Virtual K' = 3K over regions: (Ahi,Whi), (Alo,Whi), (Ahi,Wlo).
// cp.async double-buffered, XOR-swizzled smem, ldmatrix + mma.m16n8k16.
// OUTMODE 0: write hi/lo fp16 split (out0/out1). OUTMODE 1: single fp16 (out0).
// ============================================================================
template<int OUTMODE>
__global__ void __launch_bounds__(256) mma_gemm(
    const __half* __restrict__ Ahi, const __half* __restrict__ Alo,
    const __half* __restrict__ Whi, const __half* __restrict__ Wlo,
    const float* __restrict__ bias,
    __half* __restrict__ out0, __half* __restrict__ out1,
    int M, int K, int NOUT)
{
    constexpr int BM = 128, BN = 64, BK = 64;
    __shared__ __align__(16) __half sA[2][BM * BK];   // 32 KB
    __shared__ __align__(16) __half sB[2][BN * BK];   // 16 KB

    const int tid  = threadIdx.x;
    const int lane = tid & 31;
    const int warp = tid >> 5;
    const int wm   = (warp & 1) * 64;
    const int wn   = (warp >> 1) * 16;
    const int bm   = blockIdx.x * BM;
    const int bn   = blockIdx.y * BN;
    const int nch  = (3 * K) / BK;

    const int chunk = tid & 7;       // 16B chunk within a 128B row
    const int rbase = tid >> 3;      // 0..31

    float c[4][2][4];
    #pragma unroll
    for (int i = 0; i < 4; i++)
        #pragma unroll
        for (int j = 0; j < 2; j++)
            #pragma unroll
            for (int q = 0; q < 4; q++) c[i][j][q] = 0.f;

    auto issue = [&](int ch) {
        int buf = ch & 1;
        int k0v = ch * BK;
        int region = k0v / K;
        int kreal  = k0v - region * K;
        const __half* As = (region == 1) ? Alo : Ahi;
        const __half* Ws = (region == 2) ? Wlo : Whi;
        uint32_t baseA = sptr(&sA[buf][0]);
        uint32_t baseB = sptr(&sB[buf][0]);
        #pragma unroll
        for (int i = 0; i < 4; i++) {
            int row = rbase + 32 * i;
            int gm  = bm + row;
            bool ok = gm < M;
            const __half* src = As + (size_t)(ok ? gm : (M - 1)) * K + kreal + chunk * 8;
            cpa16(baseA + row * 128 + ((chunk ^ (row & 7)) << 4), src, ok);
        }
        #pragma unroll
        for (int i = 0; i < 2; i++) {
            int row = rbase + 32 * i;
            const __half* src = Ws + (size_t)(bn + row) * K + kreal + chunk * 8;
            cpa16(baseB + row * 128 + ((chunk ^ (row & 7)) << 4), src, true);
        }
        cpa_commit();
    };

    auto compute = [&](int buf) {
        uint32_t baseA = sptr(&sA[buf][0]);
        uint32_t baseB = sptr(&sB[buf][0]);
        #pragma unroll
        for (int kk = 0; kk < 4; kk++) {
            uint32_t b0, b1, b2, b3;
            {
                int row = wn + (lane & 15);
                int cl  = kk * 2 + (lane >> 4);
                uint32_t p = baseB + row * 128 + ((cl ^ (row & 7)) << 4);
                asm volatile("ldmatrix.sync.aligned.m8n8.x4.shared.b16 {%0,%1,%2,%3}, [%4];"
                             : "=r"(b0), "=r"(b1), "=r"(b2), "=r"(b3) : "r"(p));
            }
            #pragma unroll
            for (int fi = 0; fi < 4; fi++) {
                uint32_t a0, a1, a2, a3;
                int row = wm + fi * 16 + (lane & 15);
                int cl  = kk * 2 + (lane >> 4);
                uint32_t p = baseA + row * 128 + ((cl ^ (row & 7)) << 4);
                asm volatile("ldmatrix.sync.aligned.m8n8.x4.shared.b16 {%0,%1,%2,%3}, [%4];"
                             : "=r"(a0), "=r"(a1), "=r"(a2), "=r"(a3) : "r"(p));
                asm volatile("mma.sync.aligned.m16n8k16.row.col.f32.f16.f16.f32 "
                             "{%0,%1,%2,%3}, {%4,%5,%6,%7}, {%8,%9}, {%0,%1,%2,%3};"
                             : "+f"(c[fi][0][0]), "+f"(c[fi][0][1]), "+f"(c[fi][0][2]), "+f"(c[fi][0][3])
                             : "r"(a0), "r"(a1), "r"(a2), "r"(a3), "r"(b0), "r"(b2));
                asm volatile("mma.sync.aligned.m16n8k16.row.col.f32.f16.f16.f32 "
                             "{%0,%1,%2,%3}, {%4,%5,%6,%7}, {%8,%9}, {%0,%1,%2,%3};"
                             : "+f"(c[fi][1][0]), "+f"(c[fi][1][1]), "+f"(c[fi][1][2]), "+f"(c[fi][1][3])
                             : "r"(a0), "r"(a1), "r"(a2), "r"(a3), "r"(b1), "r"(b3));
            }
        }
    };

    issue(0);
    if (nch > 1) issue(1);
    for (int ch = 0; ch < nch; ch++) {
        if (ch + 1 < nch) asm volatile("cp.async.wait_group 1;" ::: "memory");
        else              asm volatile("cp.async.wait_group 0;" ::: "memory");
        __syncthreads();
        compute(ch & 1);
        __syncthreads();
        if (ch + 2 < nch) issue(ch + 2);
    }

    // ---- epilogue ----
    #pragma unroll
    for (int fi = 0; fi < 4; fi++) {
        int row0 = bm + wm + fi * 16 + (lane >> 2);
        #pragma unroll
        for (int fj = 0; fj < 2; fj++) {
            int col = bn + wn + fj * 8 + (lane & 3) * 2;
            float bx = bias[col], by = bias[col + 1];
            float v0 = c[fi][fj][0] + bx, v1 = c[fi][fj][1] + by;
            float v2 = c[fi][fj][2] + bx, v3 = c[fi][fj][3] + by;
            if (OUTMODE == 1) {
                if (row0 < M)
                    *reinterpret_cast<__half2*>(&out0[(size_t)row0 * NOUT + col]) = __floats2half2_rn(v0, v1);
                if (row0 + 8 < M)
                    *reinterpret_cast<__half2*>(&out0[(size_t)(row0 + 8) * NOUT + col]) = __floats2half2_rn(v2, v3);
            } else {
                __half h0 = __float2half_rn(v0), h1 = __float2half_rn(v1);
                __half h2 = __float2half_rn(v2), h3 = __float2half_rn(v3);
                __half l0 = __float2half_rn(v0 - __half2float(h0));
                __half l1 = __float2half_rn(v1 - __half2float(h1));
                __half l2 = __float2half_rn(v2 - __half2float(h2));
                __half l3 = __float2half_rn(v3 - __half2float(h3));
                if (row0 < M) {
                    *reinterpret_cast<__half2*>(&out0[(size_t)row0 * NOUT + col]) = __halves2half2(h0, h1);
                    *reinterpret_cast<__half2*>(&out1[(size_t)row0 * NOUT + col]) = __halves2half2(l0, l1);
                }
                if (row0 + 8 < M) {
                    *reinterpret_cast<__half2*>(&out0[(size_t)(row0 + 8) * NOUT + col]) = __halves2half2(h2, h3);
                    *reinterpret_cast<__half2*>(&out1[(size_t)(row0 + 8) * NOUT + col]) = __halves2half2(l2, l3);
                }
            }
        }
    }
}

// ============================================================================
// CSR build
// ============================================================================
__global__ void zero_cnt_kernel() {
    int i = blockIdx.x * blockDim.x + threadIdx.x;
    if (i < NNODES) g_cnt[i] = 0;
}

__global__ void hist_kernel(const int* __restrict__ ei) {
    int e = blockIdx.x * blockDim.x + threadIdx.x;
    if (e < NEDGES) atomicAdd(&g_cnt[ei[NEDGES + e]], 1);
}

__global__ void scan_kernel() {  // 1 block, 1024 threads, warp-shuffle scan
    __shared__ int wsum[32];
    __shared__ int carry_s;
    const int t = threadIdx.x, lane = t & 31, w = t >> 5;
    if (t == 0) carry_s = 0;
    __syncthreads();
    for (int base = 0; base < NNODES; base += 1024) {
        int i = base + t;
        int v = (i < NNODES) ? g_cnt[i] : 0;
        int x = v;
        #pragma unroll
        for (int o = 1; o < 32; o <<= 1) {
            int y = __shfl_up_sync(0xffffffffu, x, o);
            if (lane >= o) x += y;
        }
        if (lane == 31) wsum[w] = x;
        __syncthreads();
        if (w == 0) {
            int s = wsum[lane];
            #pragma unroll
            for (int o = 1; o < 32; o <<= 1) {
                int y = __shfl_up_sync(0xffffffffu, s, o);
                if (lane >= o) s += y;
            }
            wsum[lane] = s;
        }
        __syncthreads();
        int incl  = x + (w > 0 ? wsum[w - 1] : 0);
        int carry = carry_s;
        if (i < NNODES) { g_rowptr[i] = carry + incl - v; g_cnt[i] = 0; }
        __syncthreads();
        if (t == 1023) carry_s = carry + incl;
        __syncthreads();
    }
    if (t == 0) g_rowptr[NNODES] = carry_s;
}

__global__ void scatter_kernel(const int* __restrict__ ei) {
    int e = blockIdx.x * blockDim.x + threadIdx.x;
    if (e < NEDGES) {
        int s = ei[e];
        int d = ei[NEDGES + e];
        int pos = g_rowptr[d] + atomicAdd(&g_cnt[d], 1);
        g_col[pos] = s;
    }
}

// ============================================================================
// Fused score + aggregate: one warp per dst node (CSR), no atomics.
// H reconstructed as Hhi + Hlo (full fp32 accuracy in messages).
// MODE 0: write relu-split hi/lo fp16 (next layer input).
// MODE 1: write fp32 (final output).
// ============================================================================
template<int MODE>
__global__ void __launch_bounds__(256) agg_kernel(
    const __half* __restrict__ AB,
    const __half* __restrict__ Hhi, const __half* __restrict__ Hlo,
    const float* __restrict__ w2, const float* __restrict__ b2,
    float* __restrict__ outf, __half* __restrict__ ohi, __half* __restrict__ olo)
{
    const int lane = threadIdx.x & 31;
    const int d    = blockIdx.x * (blockDim.x >> 5) + (threadIdx.x >> 5);
    if (d >= NNODES) return;

    const float4 w0 = *reinterpret_cast<const float4*>(&w2[lane * 8]);
    const float4 w1 = *reinterpret_cast<const float4*>(&w2[lane * 8 + 4]);
    const float  bb = b2[0];

    uint4 araw = *reinterpret_cast<const uint4*>(&AB[(size_t)d * (2 * CH) + lane * 8]);
    float2 a0 = __half22float2(*reinterpret_cast<__half2*>(&araw.x));
    float2 a1 = __half22float2(*reinterpret_cast<__half2*>(&araw.y));
    float2 a2 = __half22float2(*reinterpret_cast<__half2*>(&araw.z));
    float2 a3 = __half22float2(*reinterpret_cast<__half2*>(&araw.w));

    float acc0 = 0.f, acc1 = 0.f, acc2 = 0.f, acc3 = 0.f;
    float acc4 = 0.f, acc5 = 0.f, acc6 = 0.f, acc7 = 0.f;

    const int beg = g_rowptr[d];
    const int end = g_rowptr[d + 1];

    for (int i = beg - 1; i < end; ++i) {
        int s = (i < beg) ? d : g_col[i];

        uint4 braw = *reinterpret_cast<const uint4*>(&AB[(size_t)s * (2 * CH) + CH + lane * 8]);
        uint4 hraw = *reinterpret_cast<const uint4*>(&Hhi[(size_t)s * CH + lane * 8]);
        uint4 lraw = *reinterpret_cast<const uint4*>(&Hlo[(size_t)s * CH + lane * 8]);

        float2 b0 = __half22float2(*reinterpret_cast<__half2*>(&braw.x));
        float2 b1 = __half22float2(*reinterpret_cast<__half2*>(&braw.y));
        float2 b2v = __half22float2(*reinterpret_cast<__half2*>(&braw.z));
        float2 b3 = __half22float2(*reinterpret_cast<__half2*>(&braw.w));

        float p;
        p  = fmaxf(a0.x + b0.x, 0.f) * w0.x;
        p += fmaxf(a0.y + b0.y, 0.f) * w0.y;
        p += fmaxf(a1.x + b1.x, 0.f) * w0.z;
        p += fmaxf(a1.y + b1.y, 0.f) * w0.w;
        p += fmaxf(a2.x + b2v.x, 0.f) * w1.x;
        p += fmaxf(a2.y + b2v.y, 0.f) * w1.y;
        p += fmaxf(a3.x + b3.x, 0.f) * w1.z;
        p += fmaxf(a3.y + b3.y, 0.f) * w1.w;

        #pragma unroll
        for (int off = 16; off > 0; off >>= 1)
            p += __shfl_xor_sync(0xffffffffu, p, off);

        float score = 1.f / (1.f + __expf(-(p + bb)));

        float2 h0 = __half22float2(*reinterpret_cast<__half2*>(&hraw.x));
        float2 h1 = __half22float2(*reinterpret_cast<__half2*>(&hraw.y));
        float2 h2 = __half22float2(*reinterpret_cast<__half2*>(&hraw.z));
        float2 h3 = __half22float2(*reinterpret_cast<__half2*>(&hraw.w));
        float2 l0 = __half22float2(*reinterpret_cast<__half2*>(&lraw.x));
        float2 l1 = __half22float2(*reinterpret_cast<__half2*>(&lraw.y));
        float2 l2 = __half22float2(*reinterpret_cast<__half2*>(&lraw.z));
        float2 l3 = __half22float2(*reinterpret_cast<__half2*>(&lraw.w));

        acc0 = fmaf(score, h0.x + l0.x, acc0);
        acc1 = fmaf(score, h0.y + l0.y, acc1);
        acc2 = fmaf(score, h1.x + l1.x, acc2);
        acc3 = fmaf(score, h1.y + l1.y, acc3);
        acc4 = fmaf(score, h2.x + l2.x, acc4);
        acc5 = fmaf(score, h2.y + l2.y, acc5);
        acc6 = fmaf(score, h3.x + l3.x, acc6);
        acc7 = fmaf(score, h3.y + l3.y, acc7);
    }

    if (MODE == 1) {
        float* op = &outf[(size_t)d * CH + lane * 8];
        *reinterpret_cast<float4*>(op)     = make_float4(acc0, acc1, acc2, acc3);
        *reinterpret_cast<float4*>(op + 4) = make_float4(acc4, acc5, acc6, acc7);
    } else {
        float r[8] = {fmaxf(acc0, 0.f), fmaxf(acc1, 0.f), fmaxf(acc2, 0.f), fmaxf(acc3, 0.f),
                      fmaxf(acc4, 0.f), fmaxf(acc5, 0.f), fmaxf(acc6, 0.f), fmaxf(acc7, 0.f)};
        __half h[8], l[8];
        #pragma unroll
        for (int q = 0; q < 8; q++) {
            h[q] = __float2half_rn(r[q]);
            l[q] = __float2half_rn(r[q] - __half2float(h[q]));
        }
        uint4 hv, lv;
        hv.x = *reinterpret_cast<unsigned*>(&__halves2half2(h[0], h[1]));
        hv.y = *reinterpret_cast<unsigned*>(&__halves2half2(h[2], h[3]));
        hv.z = *reinterpret_cast<unsigned*>(&__halves2half2(h[4], h[5]));
        hv.w = *reinterpret_cast<unsigned*>(&__halves2half2(h[6], h[7]));
        lv.x = *reinterpret_cast<unsigned*>(&__halves2half2(l[0], l[1]));
        lv.y = *reinterpret_cast<unsigned*>(&__halves2half2(l[2], l[3]));
        lv.z = *reinterpret_cast<unsigned*>(&__halves2half2(l[4], l[5]));
        lv.w = *reinterpret_cast<unsigned*>(&__halves2half2(l[6], l[7]));
        *reinterpret_cast<uint4*>(&ohi[(size_t)d * CH + lane * 8]) = hv;
        *reinterpret_cast<uint4*>(&olo[(size_t)d * CH + lane * 8]) = lv;
    }
}

extern "C" void kernel_launch(void* const* d_in, const int* in_sizes, int n_in,
                              void* d_out, int out_size)
{
    (void)in_sizes; (void)n_in; (void)out_size;
    const float* x  = (const float*)d_in[0];
    const int*   ei = (const int*)d_in[1];
    const float* W_lin[3] = {(const float*)d_in[2],  (const float*)d_in[8],  (const float*)d_in[14]};
    const float* b_lin[3] = {(const float*)d_in[3],  (const float*)d_in[9],  (const float*)d_in[15]};
    const float* W_s1[3]  = {(const float*)d_in[4],  (const float*)d_in[10], (const float*)d_in[16]};
    const float* b_s1[3]  = {(const float*)d_in[5],  (const float*)d_in[11], (const float*)d_in[17]};
    const float* W_s2[3]  = {(const float*)d_in[6],  (const float*)d_in[12], (const float*)d_in[18]};
    const float* b_s2[3]  = {(const float*)d_in[7],  (const float*)d_in[13], (const float*)d_in[19]};

    __half *xhi, *xlo, *Hhi, *Hlo, *Ahi, *Alo, *AB, *Wlhi, *Wllo, *Wshi, *Wslo;
    float* bfull;
    cudaGetSymbolAddress((void**)&xhi,  g_xhi);
    cudaGetSymbolAddress((void**)&xlo,  g_xlo);
    cudaGetSymbolAddress((void**)&Hhi,  g_Hhi);
    cudaGetSymbolAddress((void**)&Hlo,  g_Hlo);
    cudaGetSymbolAddress((void**)&Ahi,  g_Ahi);
    cudaGetSymbolAddress((void**)&Alo,  g_Alo);
    cudaGetSymbolAddress((void**)&AB,   g_AB);
    cudaGetSymbolAddress((void**)&Wlhi, g_Wlhi);
    cudaGetSymbolAddress((void**)&Wllo, g_Wllo);
    cudaGetSymbolAddress((void**)&Wshi, g_Wshi);
    cudaGetSymbolAddress((void**)&Wslo, g_Wslo);
    cudaGetSymbolAddress((void**)&bfull, g_bfull);
    float* out = (float*)d_out;

    const dim3 blk(256);
    const dim3 gH((NNODES + 127) / 128, CH / 64);        // (79, 4)
    const dim3 gAB((NNODES + 127) / 128, (2 * CH) / 64); // (79, 8)
    const int  agrid = (NNODES + 7) / 8;
    const int  Kl[3] = {64, CH, CH};

    // ---- one-shot conversions ----
    cvt_split<<<(NNODES * 64 + 255) / 256, blk>>>(x, xhi, xlo, NNODES * 64);
    for (int l = 0; l < 3; l++) {
        cvt_split<<<(CH * Kl[l] + 255) / 256, blk>>>(W_lin[l], Wlhi + l * CH * CH, Wllo + l * CH * CH, CH * Kl[l]);
        cvt_ws<<<(2 * CH * CH + 255) / 256, blk>>>(W_s1[l], b_s1[l],
                                                   Wshi + l * 2 * CH * CH, Wslo + l * 2 * CH * CH,
                                                   bfull + l * 2 * CH);
    }

    // ---- CSR build (dst-keyed) ----
    zero_cnt_kernel<<<(NNODES + 255) / 256, blk>>>();
    hist_kernel<<<(NEDGES + 255) / 256, blk>>>(ei);
    scan_kernel<<<1, 1024>>>();
    scatter_kernel<<<(NEDGES + 255) / 256, blk>>>(ei);

    // ---- layer 1 ----
    mma_gemm<0><<<gH,  blk>>>(xhi, xlo, Wlhi, Wllo, b_lin[0], Hhi, Hlo, NNODES, 64, CH);
    mma_gemm<1><<<gAB, blk>>>(Hhi, Hlo, Wshi, Wslo, bfull, AB, AB, NNODES, CH, 2 * CH);
    agg_kernel<0><<<agrid, blk>>>(AB, Hhi, Hlo, W_s2[0], b_s2[0], nullptr, Ahi, Alo);

    // ---- layer 2 ----
    mma_gemm<0><<<gH,  blk>>>(Ahi, Alo, Wlhi + CH * CH, Wllo + CH * CH, b_lin[1], Hhi, Hlo, NNODES, CH, CH);
    mma_gemm<1><<<gAB, blk>>>(Hhi, Hlo, Wshi + 2 * CH * CH, Wslo + 2 * CH * CH, bfull + 2 * CH, AB, AB, NNODES, CH, 2 * CH);
    agg_kernel<0><<<agrid, blk>>>(AB, Hhi, Hlo, W_s2[1], b_s2[1], nullptr, Ahi, Alo);

    // ---- layer 3 (writes d_out) ----
    mma_gemm<0><<<gH,  blk>>>(Ahi, Alo, Wlhi + 2 * CH * CH, Wllo + 2 * CH * CH, b_lin[2], Hhi, Hlo, NNODES, CH, CH);
    mma_gemm<1><<<gAB, blk>>>(Hhi, Hlo, Wshi + 4 * CH * CH, Wslo + 4 * CH * CH, bfull + 4 * CH, AB, AB, NNODES, CH, 2 * CH);
    agg_kernel<1><<<agrid, blk>>>(AB, Hhi, Hlo, W_s2[2], b_s2[2], out, nullptr, nullptr);
}